// round 14
// baseline (speedup 1.0000x reference)
#include <cuda_runtime.h>

// OpponentModelOracle: B=4096 batches, H=W=64, C=8.
// R12 = R10 (best: 91.68us bench / 88.03us ncu) + R8's vectorized store path.
// One CTA per batch (grid=4096, dynamic scheduling). 512 threads/CTA, occ 4,
// KIT=8 (per-thread MLP=8 — proven shape). Streaming hints on both streams.
// Phase 1: ballot/popc reductions (R10); the food ballot also feeds a shared
// 4096-bit mask (one predicated STS per warp per iter — nearly free now).
// Phase 3: thread t stores floats [8t,8t+8) via 2x STG.128.CS from the mask.

#define HW    4096
#define WDIM  64
#define NTHR  512
#define KIT   8     // HW / NTHR
#define NWARP 16

__global__ void __launch_bounds__(NTHR, 4)
oracle_kernel(const float4* __restrict__ x4,
              const float*  __restrict__ opp_start,
              float*        __restrict__ out)
{
    __shared__ int s_food[NWARP], s_opp[NWARP], s_first[NWARP];
    __shared__ int s_k1[NWARP], s_v2[NWARP];
    __shared__ unsigned s_mask[HW / 32];   // bit c&31 of word c>>5 = food(cell c)

    const int t    = threadIdx.x;
    const int warp = t >> 5;
    const int lane = t & 31;
    const long long b = blockIdx.x;

    const float4* xb = x4 + b * (long long)(HW * 2);   // 2 float4 per cell

    // ---------------- Phase 1: masks + counts + first opponent -------------
    // cell = warp*32 + k*512 + lane -> warp's 32 lanes are consecutive cells.
    int foodbits = 0;            // bit k: this thread's cell k is food
    int cf = 0, co = 0;          // warp totals (lane-invariant via ballot)
    int fo = 0x7FFFFFFF;         // warp's first opp cell (lane-invariant)

    #pragma unroll
    for (int k = 0; k < KIT; k++) {
        const int cell = t + (k << 9);
        float4 v = __ldcs(&xb[(long long)cell * 2]);   // streaming: ch 0..3
        const int food = (v.y == 1.0f);
        const int opp  = (v.w == 1.0f);
        foodbits |= food << k;
        const unsigned bf = __ballot_sync(0xFFFFFFFFu, food);
        const unsigned bo = __ballot_sync(0xFFFFFFFFu, opp);
        cf += __popc(bf);
        co += __popc(bo);
        if (bo) {
            const int c0 = (warp << 5) + (k << 9) + (__ffs(bo) - 1);
            if (c0 < fo) fo = c0;
        }
        if (lane == k) s_mask[warp + (k << 4)] = bf;   // word = cell>>5
    }
    if (lane == 0) { s_food[warp] = cf; s_opp[warp] = co; s_first[warp] = fo; }
    __syncthreads();

    int n_food = 0, n_opp = 0, first = 0x7FFFFFFF;
    #pragma unroll
    for (int i = 0; i < NWARP; i++) {
        n_food += s_food[i];
        n_opp  += s_opp[i];
        if (s_first[i] < first) first = s_first[i];
    }
    if (first == 0x7FFFFFFF) first = 0;   // jnp.argmax(all-false) == 0
    const int orow = first >> 6;
    const int ocol = first & (WDIM - 1);

    // ---------------- Phase 2: two smallest distances over food cells ------
    // key = (dsq << 12) | idx  -> lexicographic (distance, row-major idx) min,
    // matching argmin-first-occurrence semantics. dsq <= 7938 < 2^13.
    int k1 = 0x7FFFFFFF;   // packed best
    int v2 = 0x7FFFFFFF;   // second-best dsq (min over all but argmin element)

    #pragma unroll
    for (int k = 0; k < KIT; k++) {
        if ((foodbits >> k) & 1) {
            const int cell = t + (k << 9);
            const int dr = (cell >> 6) - orow;
            const int dc = (cell & (WDIM - 1)) - ocol;
            const int dsq = dr * dr + dc * dc;
            const int key = (dsq << 12) | cell;
            if (key < k1) { const int old = k1 >> 12; if (old < v2) v2 = old; k1 = key; }
            else          { if (dsq < v2) v2 = dsq; }
        }
    }
    #pragma unroll
    for (int o = 16; o; o >>= 1) {
        const int ok1 = __shfl_down_sync(0xFFFFFFFFu, k1, o);
        const int ov2 = __shfl_down_sync(0xFFFFFFFFu, v2, o);
        if (ov2 < v2) v2 = ov2;
        if (ok1 < k1) { const int old = k1 >> 12; if (old < v2) v2 = old; k1 = ok1; }
        else          { const int od  = ok1 >> 12; if (od  < v2) v2 = od; }
    }
    if (lane == 0) { s_k1[warp] = k1; s_v2[warp] = v2; }
    __syncthreads();

    k1 = 0x7FFFFFFF; v2 = 0x7FFFFFFF;
    #pragma unroll
    for (int i = 0; i < NWARP; i++) {
        const int ok1 = s_k1[i], ov2 = s_v2[i];
        if (ov2 < v2) v2 = ov2;
        if (ok1 < k1) { const int old = k1 >> 12; if (old < v2) v2 = old; k1 = ok1; }
        else          { const int od  = ok1 >> 12; if (od  < v2) v2 = od; }
    }

    // ---------------- Branch flags (computed redundantly by all threads) ---
    const float min1 = __fsqrt_rn((float)(k1 >> 12));
    const float min2 = __fsqrt_rn((float)v2);
    const float diff = min2 - min1;
    const int   min_idx = k1 & (HW - 1);

    const float os0 = __ldg(&opp_start[0]);
    const float os1 = __ldg(&opp_start[1]);
    const bool matches   = ((float)orow == os0) && ((float)ocol == os1);
    const bool branchA   = (n_food > 1) && (n_opp > 0) && !matches;
    const bool ambiguous = (branchA && (diff < 0.1f)) || ((n_food > 1) && !branchA);
    const bool pick      = (branchA && (diff >= 0.1f)) || (n_food == 1);

    // ---------------- Phase 3: vectorized streaming write ------------------
    // Thread t owns output floats [8t, 8t+8): food bits are byte (t&3) of
    // shared word t>>2. Two STG.128.CS per thread, fully coalesced.
    {
        const unsigned m8 = (s_mask[t >> 2] >> ((t & 3) * 8)) & 0xFFu;
        const int base = t << 3;
        float4* ob4 = (float4*)(out + b * (long long)HW + base);
        float r[8];
        #pragma unroll
        for (int j = 0; j < 8; j++) {
            int hit;
            if (ambiguous)      hit = (m8 >> j) & 1;
            else if (pick)      hit = ((base + j) == min_idx);
            else                hit = 0;
            r[j] = hit ? 10.0f : -10.0f;
        }
        __stcs(&ob4[0], make_float4(r[0], r[1], r[2], r[3]));
        __stcs(&ob4[1], make_float4(r[4], r[5], r[6], r[7]));
    }
}

extern "C" void kernel_launch(void* const* d_in, const int* in_sizes, int n_in,
                              void* d_out, int out_size)
{
    // metadata order: x [B,H,W,C] f32, opp_start [2] f32 — disambiguate by size.
    int xi = 0, si = 1;
    if (n_in >= 2 && in_sizes[0] <= 2) { xi = 1; si = 0; }
    const float4* x   = (const float4*)d_in[xi];
    const float*  ops = (const float*)d_in[si];
    float* out = (float*)d_out;

    oracle_kernel<<<4096, NTHR>>>(x, ops, out);
}

// round 15
// speedup vs baseline: 1.0003x; 1.0003x over previous
#include <cuda_runtime.h>

// OpponentModelOracle: B=4096 batches, H=W=64, C=8.
// R14 = R12 (session-best ncu: 86.98us, DRAM 83.8%) re-benched with one fix:
// opp_start scalar loads hoisted to kernel entry so they overlap the main
// load stream instead of stalling the post-reduction epilogue (~250-600 cyc
// dependent load on every CTA's critical path).
// One CTA per batch (grid=4096, dynamic scheduling). 512 threads/CTA, occ 4,
// KIT=8 (per-thread MLP=8). Streaming hints on both global streams.
// Phase 1: ballot/popc reductions; food ballots also build a shared 4096-bit
// mask (one predicated STS per warp per iter).
// Phase 3: thread t stores floats [8t,8t+8) via 2x STG.128.CS from the mask.

#define HW    4096
#define WDIM  64
#define NTHR  512
#define KIT   8     // HW / NTHR
#define NWARP 16

__global__ void __launch_bounds__(NTHR, 4)
oracle_kernel(const float4* __restrict__ x4,
              const float*  __restrict__ opp_start,
              float*        __restrict__ out)
{
    __shared__ int s_food[NWARP], s_opp[NWARP], s_first[NWARP];
    __shared__ int s_k1[NWARP], s_v2[NWARP];
    __shared__ unsigned s_mask[HW / 32];   // bit c&31 of word c>>5 = food(cell c)

    const int t    = threadIdx.x;
    const int warp = t >> 5;
    const int lane = t & 31;
    const long long b = blockIdx.x;

    // Hoisted: issue now, consumed after phase 2 — covered by the load stream.
    const float os0 = __ldg(&opp_start[0]);
    const float os1 = __ldg(&opp_start[1]);

    const float4* xb = x4 + b * (long long)(HW * 2);   // 2 float4 per cell

    // ---------------- Phase 1: masks + counts + first opponent -------------
    // cell = warp*32 + k*512 + lane -> warp's 32 lanes are consecutive cells.
    int foodbits = 0;            // bit k: this thread's cell k is food
    int cf = 0, co = 0;          // warp totals (lane-invariant via ballot)
    int fo = 0x7FFFFFFF;         // warp's first opp cell (lane-invariant)

    #pragma unroll
    for (int k = 0; k < KIT; k++) {
        const int cell = t + (k << 9);
        float4 v = __ldcs(&xb[(long long)cell * 2]);   // streaming: ch 0..3
        const int food = (v.y == 1.0f);
        const int opp  = (v.w == 1.0f);
        foodbits |= food << k;
        const unsigned bf = __ballot_sync(0xFFFFFFFFu, food);
        const unsigned bo = __ballot_sync(0xFFFFFFFFu, opp);
        cf += __popc(bf);
        co += __popc(bo);
        if (bo) {
            const int c0 = (warp << 5) + (k << 9) + (__ffs(bo) - 1);
            if (c0 < fo) fo = c0;
        }
        if (lane == k) s_mask[warp + (k << 4)] = bf;   // word = cell>>5
    }
    if (lane == 0) { s_food[warp] = cf; s_opp[warp] = co; s_first[warp] = fo; }
    __syncthreads();

    int n_food = 0, n_opp = 0, first = 0x7FFFFFFF;
    #pragma unroll
    for (int i = 0; i < NWARP; i++) {
        n_food += s_food[i];
        n_opp  += s_opp[i];
        if (s_first[i] < first) first = s_first[i];
    }
    if (first == 0x7FFFFFFF) first = 0;   // jnp.argmax(all-false) == 0
    const int orow = first >> 6;
    const int ocol = first & (WDIM - 1);

    // ---------------- Phase 2: two smallest distances over food cells ------
    // key = (dsq << 12) | idx  -> lexicographic (distance, row-major idx) min,
    // matching argmin-first-occurrence semantics. dsq <= 7938 < 2^13.
    int k1 = 0x7FFFFFFF;   // packed best
    int v2 = 0x7FFFFFFF;   // second-best dsq (min over all but argmin element)

    #pragma unroll
    for (int k = 0; k < KIT; k++) {
        if ((foodbits >> k) & 1) {
            const int cell = t + (k << 9);
            const int dr = (cell >> 6) - orow;
            const int dc = (cell & (WDIM - 1)) - ocol;
            const int dsq = dr * dr + dc * dc;
            const int key = (dsq << 12) | cell;
            if (key < k1) { const int old = k1 >> 12; if (old < v2) v2 = old; k1 = key; }
            else          { if (dsq < v2) v2 = dsq; }
        }
    }
    #pragma unroll
    for (int o = 16; o; o >>= 1) {
        const int ok1 = __shfl_down_sync(0xFFFFFFFFu, k1, o);
        const int ov2 = __shfl_down_sync(0xFFFFFFFFu, v2, o);
        if (ov2 < v2) v2 = ov2;
        if (ok1 < k1) { const int old = k1 >> 12; if (old < v2) v2 = old; k1 = ok1; }
        else          { const int od  = ok1 >> 12; if (od  < v2) v2 = od; }
    }
    if (lane == 0) { s_k1[warp] = k1; s_v2[warp] = v2; }
    __syncthreads();

    k1 = 0x7FFFFFFF; v2 = 0x7FFFFFFF;
    #pragma unroll
    for (int i = 0; i < NWARP; i++) {
        const int ok1 = s_k1[i], ov2 = s_v2[i];
        if (ov2 < v2) v2 = ov2;
        if (ok1 < k1) { const int old = k1 >> 12; if (old < v2) v2 = old; k1 = ok1; }
        else          { const int od  = ok1 >> 12; if (od  < v2) v2 = od; }
    }

    // ---------------- Branch flags (computed redundantly by all threads) ---
    const float min1 = __fsqrt_rn((float)(k1 >> 12));
    const float min2 = __fsqrt_rn((float)v2);
    const float diff = min2 - min1;
    const int   min_idx = k1 & (HW - 1);

    const bool matches   = ((float)orow == os0) && ((float)ocol == os1);
    const bool branchA   = (n_food > 1) && (n_opp > 0) && !matches;
    const bool ambiguous = (branchA && (diff < 0.1f)) || ((n_food > 1) && !branchA);
    const bool pick      = (branchA && (diff >= 0.1f)) || (n_food == 1);

    // ---------------- Phase 3: vectorized streaming write ------------------
    // Thread t owns output floats [8t, 8t+8): food bits are byte (t&3) of
    // shared word t>>2. Two STG.128.CS per thread, fully coalesced.
    {
        const unsigned m8 = (s_mask[t >> 2] >> ((t & 3) * 8)) & 0xFFu;
        const int base = t << 3;
        float4* ob4 = (float4*)(out + b * (long long)HW + base);
        float r[8];
        #pragma unroll
        for (int j = 0; j < 8; j++) {
            int hit;
            if (ambiguous)      hit = (m8 >> j) & 1;
            else if (pick)      hit = ((base + j) == min_idx);
            else                hit = 0;
            r[j] = hit ? 10.0f : -10.0f;
        }
        __stcs(&ob4[0], make_float4(r[0], r[1], r[2], r[3]));
        __stcs(&ob4[1], make_float4(r[4], r[5], r[6], r[7]));
    }
}

extern "C" void kernel_launch(void* const* d_in, const int* in_sizes, int n_in,
                              void* d_out, int out_size)
{
    // metadata order: x [B,H,W,C] f32, opp_start [2] f32 — disambiguate by size.
    int xi = 0, si = 1;
    if (n_in >= 2 && in_sizes[0] <= 2) { xi = 1; si = 0; }
    const float4* x   = (const float4*)d_in[xi];
    const float*  ops = (const float*)d_in[si];
    float* out = (float*)d_out;

    oracle_kernel<<<4096, NTHR>>>(x, ops, out);
}

// round 17
// speedup vs baseline: 1.0076x; 1.0073x over previous
#include <cuda_runtime.h>

// OpponentModelOracle: B=4096 batches, H=W=64, C=8.
// R15 = R10 (bench-best: 91.68us) + hoisted opp_start loads (from R14).
// Two consistent bench samples showed the vectorized-store epilogue (R12/R14)
// costs ~1.2us vs scalar stores despite one flattering ncu capture; ncu
// single-launch noise is ~±2us, so bench mean is the discriminator. Revert
// to scalar predicated stores.
// One CTA per batch (grid=4096, dynamic scheduling). 512 threads/CTA, occ 4,
// KIT=8 (per-thread MLP=8 — proven shape). Streaming hints on both streams.
// Phase 1: ballot/popc reductions (no shuffle tree, no dependent chains).

#define HW    4096
#define WDIM  64
#define NTHR  512
#define KIT   8     // HW / NTHR
#define NWARP 16

__global__ void __launch_bounds__(NTHR, 4)
oracle_kernel(const float4* __restrict__ x4,
              const float*  __restrict__ opp_start,
              float*        __restrict__ out)
{
    __shared__ int s_food[NWARP], s_opp[NWARP], s_first[NWARP];
    __shared__ int s_k1[NWARP], s_v2[NWARP];

    const int t    = threadIdx.x;
    const int warp = t >> 5;
    const int lane = t & 31;
    const long long b = blockIdx.x;

    // Hoisted: issue now, consumed after phase 2 — covered by the load stream.
    const float os0 = __ldg(&opp_start[0]);
    const float os1 = __ldg(&opp_start[1]);

    const float4* xb = x4 + b * (long long)(HW * 2);   // 2 float4 per cell

    // ---------------- Phase 1: masks + counts + first opponent -------------
    // cell = warp*32 + k*512 + lane -> warp's 32 lanes are consecutive cells.
    int foodbits = 0;            // bit k: this thread's cell k is food
    int cf = 0, co = 0;          // warp totals (lane-invariant via ballot)
    int fo = 0x7FFFFFFF;         // warp's first opp cell (lane-invariant)

    #pragma unroll
    for (int k = 0; k < KIT; k++) {
        const int cell = t + (k << 9);
        float4 v = __ldcs(&xb[(long long)cell * 2]);   // streaming: ch 0..3
        const int food = (v.y == 1.0f);
        const int opp  = (v.w == 1.0f);
        foodbits |= food << k;
        const unsigned bf = __ballot_sync(0xFFFFFFFFu, food);
        const unsigned bo = __ballot_sync(0xFFFFFFFFu, opp);
        cf += __popc(bf);
        co += __popc(bo);
        if (bo) {
            const int c0 = (warp << 5) + (k << 9) + (__ffs(bo) - 1);
            if (c0 < fo) fo = c0;
        }
    }
    if (lane == 0) { s_food[warp] = cf; s_opp[warp] = co; s_first[warp] = fo; }
    __syncthreads();

    int n_food = 0, n_opp = 0, first = 0x7FFFFFFF;
    #pragma unroll
    for (int i = 0; i < NWARP; i++) {
        n_food += s_food[i];
        n_opp  += s_opp[i];
        if (s_first[i] < first) first = s_first[i];
    }
    if (first == 0x7FFFFFFF) first = 0;   // jnp.argmax(all-false) == 0
    const int orow = first >> 6;
    const int ocol = first & (WDIM - 1);

    // ---------------- Phase 2: two smallest distances over food cells ------
    // key = (dsq << 12) | idx  -> lexicographic (distance, row-major idx) min,
    // matching argmin-first-occurrence semantics. dsq <= 7938 < 2^13.
    int k1 = 0x7FFFFFFF;   // packed best
    int v2 = 0x7FFFFFFF;   // second-best dsq (min over all but argmin element)

    #pragma unroll
    for (int k = 0; k < KIT; k++) {
        if ((foodbits >> k) & 1) {
            const int cell = t + (k << 9);
            const int dr = (cell >> 6) - orow;
            const int dc = (cell & (WDIM - 1)) - ocol;
            const int dsq = dr * dr + dc * dc;
            const int key = (dsq << 12) | cell;
            if (key < k1) { const int old = k1 >> 12; if (old < v2) v2 = old; k1 = key; }
            else          { if (dsq < v2) v2 = dsq; }
        }
    }
    #pragma unroll
    for (int o = 16; o; o >>= 1) {
        const int ok1 = __shfl_down_sync(0xFFFFFFFFu, k1, o);
        const int ov2 = __shfl_down_sync(0xFFFFFFFFu, v2, o);
        if (ov2 < v2) v2 = ov2;
        if (ok1 < k1) { const int old = k1 >> 12; if (old < v2) v2 = old; k1 = ok1; }
        else          { const int od  = ok1 >> 12; if (od  < v2) v2 = od; }
    }
    if (lane == 0) { s_k1[warp] = k1; s_v2[warp] = v2; }
    __syncthreads();

    k1 = 0x7FFFFFFF; v2 = 0x7FFFFFFF;
    #pragma unroll
    for (int i = 0; i < NWARP; i++) {
        const int ok1 = s_k1[i], ov2 = s_v2[i];
        if (ov2 < v2) v2 = ov2;
        if (ok1 < k1) { const int old = k1 >> 12; if (old < v2) v2 = old; k1 = ok1; }
        else          { const int od  = ok1 >> 12; if (od  < v2) v2 = od; }
    }

    // ---------------- Branch flags (computed redundantly by all threads) ---
    const float min1 = __fsqrt_rn((float)(k1 >> 12));
    const float min2 = __fsqrt_rn((float)v2);
    const float diff = min2 - min1;
    const int   min_idx = k1 & (HW - 1);

    const bool matches   = ((float)orow == os0) && ((float)ocol == os1);
    const bool branchA   = (n_food > 1) && (n_opp > 0) && !matches;
    const bool ambiguous = (branchA && (diff < 0.1f)) || ((n_food > 1) && !branchA);
    const bool pick      = (branchA && (diff >= 0.1f)) || (n_food == 1);

    // ---------------- Phase 3: streaming coalesced write -------------------
    float* ob = out + b * (long long)HW;
    #pragma unroll
    for (int k = 0; k < KIT; k++) {
        const int cell = t + (k << 9);
        const int food = (foodbits >> k) & 1;
        int hit;
        if (ambiguous)      hit = food;
        else if (pick)      hit = (cell == min_idx);
        else                hit = 0;
        __stcs(&ob[cell], hit ? 10.0f : -10.0f);
    }
}

extern "C" void kernel_launch(void* const* d_in, const int* in_sizes, int n_in,
                              void* d_out, int out_size)
{
    // metadata order: x [B,H,W,C] f32, opp_start [2] f32 — disambiguate by size.
    int xi = 0, si = 1;
    if (n_in >= 2 && in_sizes[0] <= 2) { xi = 1; si = 0; }
    const float4* x   = (const float4*)d_in[xi];
    const float*  ops = (const float*)d_in[si];
    float* out = (float*)d_out;

    oracle_kernel<<<4096, NTHR>>>(x, ops, out);
}